// round 3
// baseline (speedup 1.0000x reference)
#include <cuda_runtime.h>
#include <cstdint>

// Problem constants
#define M_Q 65536
#define N_K 65536
#define KNB 16
#define CH  64
#define WST 68   // padded row stride for transposed weight tiles (conflict-free LDS.128)

// ---------------------------------------------------------------------------
// Device-global scratch (allocation-free workaround per harness rules)
// ---------------------------------------------------------------------------
__device__ float g_A  [CH * CH];        // A = Wqk @ Wg1
__device__ float g_QG [M_Q * CH];       // (q+q_pos)@A + bg1
__device__ float g_KG [N_K * CH];       // (k+k_pos)@A
__device__ float g_RES[M_Q * CH];       // pre-output aggregate
__device__ int   g_mask_mode;           // 0 = uint8, 1 = int32, 2 = float32

// ---------------------------------------------------------------------------
// Packed fp32x2 helpers (sm_103a FFMA2 path — ptxas won't auto-fuse)
// ---------------------------------------------------------------------------
__device__ __forceinline__ unsigned long long fma2(unsigned long long a,
                                                   unsigned long long b,
                                                   unsigned long long c) {
    unsigned long long d;
    asm("fma.rn.f32x2 %0, %1, %2, %3;" : "=l"(d) : "l"(a), "l"(b), "l"(c));
    return d;
}
__device__ __forceinline__ float hsum2(unsigned long long v) {
    float lo, hi;
    asm("mov.b64 {%0, %1}, %2;" : "=f"(lo), "=f"(hi) : "l"(v));
    return lo + hi;
}

// ---------------------------------------------------------------------------
// Kernel 0: detect mask dtype (scan first M*K bytes; safe for all dtypes)
// ---------------------------------------------------------------------------
__global__ void detect_mask_kernel(const unsigned char* __restrict__ mask) {
    __shared__ int sA, sB;
    int tid = threadIdx.x;
    if (tid == 0) { sA = 0; sB = 0; }
    __syncthreads();
    const uint4* p = (const uint4*)mask;
    int nvec = (M_Q * KNB) / 16;
    int fA = 0, fB = 0;
    for (int i = tid; i < nvec; i += blockDim.x) {
        uint4 v = p[i];
        unsigned w[4] = {v.x, v.y, v.z, v.w};
#pragma unroll
        for (int j = 0; j < 4; j++) {
            if ((w[j] >> 24) == 0x3fu) fA = 1;
            if (w[j] & 0x00ffff00u)    fB = 1;
            if ((w[j] >> 24) && ((w[j] >> 24) != 0x3fu)) fB = 1;
        }
    }
    if (fA) atomicOr(&sA, 1);
    if (fB) atomicOr(&sB, 1);
    __syncthreads();
    if (tid == 0) g_mask_mode = sA ? 2 : (sB ? 0 : 1);
}

// ---------------------------------------------------------------------------
// Kernel 1: A = Wqk @ Wg1   (64x64, trivial)
// ---------------------------------------------------------------------------
__global__ void compute_A_kernel(const float* __restrict__ Wqk,
                                 const float* __restrict__ Wg1) {
    int t = blockIdx.x * blockDim.x + threadIdx.x;
    int r = t >> 6, c = t & 63;
    float s = 0.f;
#pragma unroll
    for (int u = 0; u < CH; u++) s += Wqk[r * CH + u] * Wg1[u * CH + c];
    g_A[t] = s;
}

// ---------------------------------------------------------------------------
// Kernel 2: merged projection. Rows [0,M) -> g_QG = (q+q_pos)@A + bg1
//           Rows [M,M+N) -> g_KG = (k+k_pos)@A
// 256 threads, 8 warps x 8 rows = 64 rows/block. Blocks 0..1023 q, 1024.. k.
// ---------------------------------------------------------------------------
__global__ __launch_bounds__(256) void project_kernel(
    const float* __restrict__ q, const float* __restrict__ q_pos,
    const float* __restrict__ k, const float* __restrict__ k_pos,
    const float* __restrict__ bg1)
{
    __shared__ __align__(16) float AT[CH * WST];
    __shared__ __align__(16) float rowbuf[8][8 * CH];
    __shared__ float bsh[CH];

    int tid = threadIdx.x, lane = tid & 31, wid = tid >> 5;

    for (int i = tid; i < CH * CH; i += 256) {
        int t = i >> 6, c = i & 63;
        AT[c * WST + t] = g_A[i];
    }
    if (tid < CH) bsh[tid] = bg1[tid];
    __syncthreads();

    int row0 = blockIdx.x * 64 + wid * 8;           // global row (q then k)
    bool is_q = row0 < M_Q;
    const float* src = is_q ? q : k;
    const float* pos = is_q ? q_pos : k_pos;
    float* dst       = is_q ? g_QG : g_KG;
    int r0 = is_q ? row0 : row0 - M_Q;

    float* rb = &rowbuf[wid][0];
#pragma unroll
    for (int j = 0; j < 8; j++) {
        const float2* s2 = (const float2*)(src + (size_t)(r0 + j) * CH);
        const float2* p2 = (const float2*)(pos + (size_t)(r0 + j) * CH);
        float2 a = s2[lane], b = p2[lane];
        ((float2*)(rb + j * CH))[lane] = make_float2(a.x + b.x, a.y + b.y);
    }
    __syncwarp();

    unsigned long long accA[8], accB[8];
#pragma unroll
    for (int j = 0; j < 8; j++) { accA[j] = 0ull; accB[j] = 0ull; }
    const float* wr0 = AT + lane * WST;
    const float* wr1 = AT + (lane + 32) * WST;

#pragma unroll
    for (int t4 = 0; t4 < CH; t4 += 4) {
        ulonglong2 wa = *reinterpret_cast<const ulonglong2*>(wr0 + t4);
        ulonglong2 wb = *reinterpret_cast<const ulonglong2*>(wr1 + t4);
#pragma unroll
        for (int j = 0; j < 8; j++) {
            ulonglong2 hp = *reinterpret_cast<const ulonglong2*>(rb + j * CH + t4);
            accA[j] = fma2(hp.x, wa.x, accA[j]);
            accA[j] = fma2(hp.y, wa.y, accA[j]);
            accB[j] = fma2(hp.x, wb.x, accB[j]);
            accB[j] = fma2(hp.y, wb.y, accB[j]);
        }
    }
    float b0 = is_q ? bsh[lane] : 0.f;
    float b1 = is_q ? bsh[lane + 32] : 0.f;
#pragma unroll
    for (int j = 0; j < 8; j++) {
        dst[(size_t)(r0 + j) * CH + lane]      = hsum2(accA[j]) + b0;
        dst[(size_t)(r0 + j) * CH + 32 + lane] = hsum2(accB[j]) + b1;
    }
}

// ---------------------------------------------------------------------------
// Kernel 3: fused attention core. 256 threads, 8 warps, 1 query/warp.
//   smem: Wg2^T, Wv^T (WST-padded), biases, per-warp h[16][64]
//   writes res (pre Wt) to g_RES
// ---------------------------------------------------------------------------
#define ASM_FLOATS (2 * CH * WST + 2 * CH + 8 * KNB * CH)
#define ASM_BYTES  (ASM_FLOATS * 4)

__global__ __launch_bounds__(256) void attn_kernel(
    const float* __restrict__ value, const unsigned char* __restrict__ mask,
    const int* __restrict__ knn,
    const float* __restrict__ Wg2, const float* __restrict__ bg2,
    const float* __restrict__ Wv,  const float* __restrict__ bv)
{
    extern __shared__ __align__(16) float sm[];
    float* w2t = sm;                       // [64][WST]
    float* wvt = w2t + CH * WST;
    float* bsh = wvt + CH * WST;           // bg2 | bv
    float* hb  = bsh + 2 * CH;             // 8 warps x [16][64]

    int tid = threadIdx.x, lane = tid & 31, wid = tid >> 5;

    for (int i = tid; i < CH * CH; i += 256) {
        int c = i >> 6, f = i & 63;
        w2t[f * WST + c] = Wg2[i];
        wvt[f * WST + c] = Wv[i];
    }
    if (tid < CH) {
        bsh[tid]      = bg2[tid];
        bsh[CH + tid] = bv[tid];
    }
    __syncthreads();

    int m = blockIdx.x * 8 + wid;
    float* h = hb + wid * (KNB * CH);

    // neighbor ids + mask in lanes 0..15
    int nb = 0, mk = 0;
    int mmode = g_mask_mode;
    if (lane < KNB) {
        size_t ix = (size_t)m * KNB + lane;
        nb = knn[(size_t)M_Q * KNB + ix];           // row 1 of knearest_idx
        if (mmode == 0)      mk = mask[ix] != 0;
        else if (mmode == 1) mk = ((const int*)mask)[ix] != 0;
        else                 mk = ((const float*)mask)[ix] != 0.f;
    }

    float2 qg = ((const float2*)(g_QG + (size_t)m * CH))[lane];

    // ---- Phase A: gather + relu-diff into shared ----
#pragma unroll
    for (int e = 0; e < KNB; e++) {
        int n = __shfl_sync(0xffffffffu, nb, e);
        float2 kg = ((const float2*)(g_KG + (size_t)n * CH))[lane];
        ((float2*)(h + e * CH))[lane] =
            make_float2(fmaxf(qg.x - kg.x, 0.f), fmaxf(qg.y - kg.y, 0.f));
    }
    __syncwarp();

    // ---- Phase B: logits = h @ Wg2 ----
    unsigned long long accA[KNB], accB[KNB];
#pragma unroll
    for (int e = 0; e < KNB; e++) { accA[e] = 0ull; accB[e] = 0ull; }
    {
        const float* r0 = w2t + lane * WST;
        const float* r1 = w2t + (lane + 32) * WST;
#pragma unroll
        for (int c4 = 0; c4 < CH; c4 += 4) {
            ulonglong2 wa = *reinterpret_cast<const ulonglong2*>(r0 + c4);
            ulonglong2 wb = *reinterpret_cast<const ulonglong2*>(r1 + c4);
#pragma unroll
            for (int e = 0; e < KNB; e++) {
                ulonglong2 hp = *reinterpret_cast<const ulonglong2*>(h + e * CH + c4);
                accA[e] = fma2(hp.x, wa.x, accA[e]);
                accA[e] = fma2(hp.y, wa.y, accA[e]);
                accB[e] = fma2(hp.x, wb.x, accB[e]);
                accB[e] = fma2(hp.y, wb.y, accB[e]);
            }
        }
    }

    // ---- mask + per-channel softmax over neighbors ----
    float p0[KNB], p1[KNB];
    float b0 = bsh[lane], b1 = bsh[32 + lane];
    float mx0 = -3.4e38f, mx1 = -3.4e38f;
#pragma unroll
    for (int e = 0; e < KNB; e++) {
        int mm = __shfl_sync(0xffffffffu, mk, e);
        float e0 = hsum2(accA[e]) + b0;
        float e1 = hsum2(accB[e]) + b1;
        if (mm) { e0 = -1e12f; e1 = -1e12f; }
        p0[e] = e0; p1[e] = e1;
        mx0 = fmaxf(mx0, e0); mx1 = fmaxf(mx1, e1);
    }
    float s0 = 0.f, s1 = 0.f;
#pragma unroll
    for (int e = 0; e < KNB; e++) {
        p0[e] = __expf(p0[e] - mx0); s0 += p0[e];
        p1[e] = __expf(p1[e] - mx1); s1 += p1[e];
    }
    float inv0 = 1.f / s0, inv1 = 1.f / s1;

    // ---- Phase C: stage value rows, v = value @ Wv, weighted aggregate ----
    __syncwarp();
    {
        const float4* vs4 = (const float4*)(value + (size_t)m * KNB * CH);
        float4* h4 = (float4*)h;
#pragma unroll
        for (int i = 0; i < 8; i++) h4[i * 32 + lane] = vs4[i * 32 + lane];
    }
    __syncwarp();

#pragma unroll
    for (int e = 0; e < KNB; e++) { accA[e] = 0ull; accB[e] = 0ull; }
    {
        const float* r0 = wvt + lane * WST;
        const float* r1 = wvt + (lane + 32) * WST;
#pragma unroll
        for (int c4 = 0; c4 < CH; c4 += 4) {
            ulonglong2 wa = *reinterpret_cast<const ulonglong2*>(r0 + c4);
            ulonglong2 wb = *reinterpret_cast<const ulonglong2*>(r1 + c4);
#pragma unroll
            for (int e = 0; e < KNB; e++) {
                ulonglong2 hp = *reinterpret_cast<const ulonglong2*>(h + e * CH + c4);
                accA[e] = fma2(hp.x, wa.x, accA[e]);
                accA[e] = fma2(hp.y, wa.y, accA[e]);
                accB[e] = fma2(hp.x, wb.x, accB[e]);
                accB[e] = fma2(hp.y, wb.y, accB[e]);
            }
        }
    }
    float bv0 = bsh[CH + lane], bv1 = bsh[CH + 32 + lane];
    float res0 = 0.f, res1 = 0.f;
#pragma unroll
    for (int e = 0; e < KNB; e++) {
        res0 += p0[e] * (hsum2(accA[e]) + bv0);
        res1 += p1[e] * (hsum2(accB[e]) + bv1);
    }
    g_RES[(size_t)m * CH + lane]      = res0 * inv0;
    g_RES[(size_t)m * CH + 32 + lane] = res1 * inv1;
}

// ---------------------------------------------------------------------------
// Kernel 4: out = g_RES @ Wt + bt
// ---------------------------------------------------------------------------
__global__ __launch_bounds__(256) void outproj_kernel(
    const float* __restrict__ Wt, const float* __restrict__ bt,
    float* __restrict__ out)
{
    __shared__ __align__(16) float WT[CH * WST];
    __shared__ __align__(16) float rowbuf[8][8 * CH];
    __shared__ float bsh[CH];

    int tid = threadIdx.x, lane = tid & 31, wid = tid >> 5;

    for (int i = tid; i < CH * CH; i += 256) {
        int t = i >> 6, c = i & 63;
        WT[c * WST + t] = Wt[i];
    }
    if (tid < CH) bsh[tid] = bt[tid];
    __syncthreads();

    int r0 = blockIdx.x * 64 + wid * 8;
    float* rb = &rowbuf[wid][0];
#pragma unroll
    for (int j = 0; j < 8; j++) {
        ((float2*)(rb + j * CH))[lane] =
            ((const float2*)(g_RES + (size_t)(r0 + j) * CH))[lane];
    }
    __syncwarp();

    unsigned long long accA[8], accB[8];
#pragma unroll
    for (int j = 0; j < 8; j++) { accA[j] = 0ull; accB[j] = 0ull; }
    const float* wr0 = WT + lane * WST;
    const float* wr1 = WT + (lane + 32) * WST;

#pragma unroll
    for (int t4 = 0; t4 < CH; t4 += 4) {
        ulonglong2 wa = *reinterpret_cast<const ulonglong2*>(wr0 + t4);
        ulonglong2 wb = *reinterpret_cast<const ulonglong2*>(wr1 + t4);
#pragma unroll
        for (int j = 0; j < 8; j++) {
            ulonglong2 hp = *reinterpret_cast<const ulonglong2*>(rb + j * CH + t4);
            accA[j] = fma2(hp.x, wa.x, accA[j]);
            accA[j] = fma2(hp.y, wa.y, accA[j]);
            accB[j] = fma2(hp.x, wb.x, accB[j]);
            accB[j] = fma2(hp.y, wb.y, accB[j]);
        }
    }
#pragma unroll
    for (int j = 0; j < 8; j++) {
        out[(size_t)(r0 + j) * CH + lane]      = hsum2(accA[j]) + bsh[lane];
        out[(size_t)(r0 + j) * CH + 32 + lane] = hsum2(accB[j]) + bsh[lane + 32];
    }
}

// ---------------------------------------------------------------------------
// kernel_launch
// Inputs: 0 q, 1 k, 2 value, 3 q_pos, 4 k_pos, 5 mask(bool), 6 knn(i32),
//  7 k_num, 8 Wqk, 9 bqk, 10 Wv, 11 bv, 12 Wg1, 13 bg1, 14 Wg2, 15 bg2,
//  16 Wt, 17 bt.   Output: [M, C] f32.
// ---------------------------------------------------------------------------
extern "C" void kernel_launch(void* const* d_in, const int* in_sizes, int n_in,
                              void* d_out, int out_size)
{
    const float* q      = (const float*)d_in[0];
    const float* k      = (const float*)d_in[1];
    const float* value  = (const float*)d_in[2];
    const float* q_pos  = (const float*)d_in[3];
    const float* k_pos  = (const float*)d_in[4];
    const unsigned char* mask = (const unsigned char*)d_in[5];
    const int*   knn    = (const int*)d_in[6];
    const float* Wqk    = (const float*)d_in[8];
    const float* Wv     = (const float*)d_in[10];
    const float* bv     = (const float*)d_in[11];
    const float* Wg1    = (const float*)d_in[12];
    const float* bg1    = (const float*)d_in[13];
    const float* Wg2    = (const float*)d_in[14];
    const float* bg2    = (const float*)d_in[15];
    const float* Wt     = (const float*)d_in[16];
    const float* bt     = (const float*)d_in[17];
    float* out = (float*)d_out;

    cudaFuncSetAttribute(attn_kernel,
                         cudaFuncAttributeMaxDynamicSharedMemorySize, ASM_BYTES);

    detect_mask_kernel<<<1, 1024>>>(mask);
    compute_A_kernel<<<8, 512>>>(Wqk, Wg1);
    project_kernel<<<(M_Q + N_K) / 64, 256>>>(q, q_pos, k, k_pos, bg1);
    attn_kernel<<<M_Q / 8, 256, ASM_BYTES>>>(value, mask, knn,
                                             Wg2, bg2, Wv, bv);
    outproj_kernel<<<M_Q / 64, 256>>>(Wt, bt, out);
}

// round 4
// speedup vs baseline: 1.3468x; 1.3468x over previous
#include <cuda_runtime.h>
#include <cstdint>

// Problem constants
#define M_Q 65536
#define N_K 65536
#define KNB 16
#define CH  64
#define WST 68   // padded row stride for transposed weight tiles (conflict-free LDS.128)

// ---------------------------------------------------------------------------
// Device-global scratch (allocation-free workaround per harness rules)
// ---------------------------------------------------------------------------
__device__ float g_A  [CH * CH];        // A = Wqk @ Wg1
__device__ float g_QG [M_Q * CH];       // (q+q_pos)@A + bg1
__device__ float g_KG [N_K * CH];       // (k+k_pos)@A
__device__ float g_RES[M_Q * CH];       // pre-output aggregate
__device__ int   g_mask_mode;           // 0 = uint8, 1 = int32, 2 = float32

// ---------------------------------------------------------------------------
// Packed fp32x2 helpers (sm_103a FFMA2 path — ptxas won't auto-fuse)
// ---------------------------------------------------------------------------
__device__ __forceinline__ unsigned long long fma2(unsigned long long a,
                                                   unsigned long long b,
                                                   unsigned long long c) {
    unsigned long long d;
    asm("fma.rn.f32x2 %0, %1, %2, %3;" : "=l"(d) : "l"(a), "l"(b), "l"(c));
    return d;
}
__device__ __forceinline__ float hsum2(unsigned long long v) {
    float lo, hi;
    asm("mov.b64 {%0, %1}, %2;" : "=f"(lo), "=f"(hi) : "l"(v));
    return lo + hi;
}

// ---------------------------------------------------------------------------
// Kernel 0: detect mask dtype (scan first M*K bytes; safe for all dtypes)
// ---------------------------------------------------------------------------
__global__ void detect_mask_kernel(const unsigned char* __restrict__ mask) {
    __shared__ int sA, sB;
    int tid = threadIdx.x;
    if (tid == 0) { sA = 0; sB = 0; }
    __syncthreads();
    const uint4* p = (const uint4*)mask;
    int nvec = (M_Q * KNB) / 16;
    int fA = 0, fB = 0;
    for (int i = tid; i < nvec; i += blockDim.x) {
        uint4 v = p[i];
        unsigned w[4] = {v.x, v.y, v.z, v.w};
#pragma unroll
        for (int j = 0; j < 4; j++) {
            if ((w[j] >> 24) == 0x3fu) fA = 1;
            if (w[j] & 0x00ffff00u)    fB = 1;
            if ((w[j] >> 24) && ((w[j] >> 24) != 0x3fu)) fB = 1;
        }
    }
    if (fA) atomicOr(&sA, 1);
    if (fB) atomicOr(&sB, 1);
    __syncthreads();
    if (tid == 0) g_mask_mode = sA ? 2 : (sB ? 0 : 1);
}

// ---------------------------------------------------------------------------
// Kernel 1: A = Wqk @ Wg1   (64x64, trivial)
// ---------------------------------------------------------------------------
__global__ void compute_A_kernel(const float* __restrict__ Wqk,
                                 const float* __restrict__ Wg1) {
    int t = blockIdx.x * blockDim.x + threadIdx.x;
    int r = t >> 6, c = t & 63;
    float s = 0.f;
#pragma unroll
    for (int u = 0; u < CH; u++) s += Wqk[r * CH + u] * Wg1[u * CH + c];
    g_A[t] = s;
}

// ---------------------------------------------------------------------------
// Kernel 2: merged projection. Rows [0,M) -> g_QG = (q+q_pos)@A + bg1
//           Rows [M,M+N) -> g_KG = (k+k_pos)@A
// ---------------------------------------------------------------------------
__global__ __launch_bounds__(256) void project_kernel(
    const float* __restrict__ q, const float* __restrict__ q_pos,
    const float* __restrict__ k, const float* __restrict__ k_pos,
    const float* __restrict__ bg1)
{
    __shared__ __align__(16) float AT[CH * WST];
    __shared__ __align__(16) float rowbuf[8][8 * CH];
    __shared__ float bsh[CH];

    int tid = threadIdx.x, lane = tid & 31, wid = tid >> 5;

    for (int i = tid; i < CH * CH; i += 256) {
        int t = i >> 6, c = i & 63;
        AT[c * WST + t] = g_A[i];
    }
    if (tid < CH) bsh[tid] = bg1[tid];
    __syncthreads();

    int row0 = blockIdx.x * 64 + wid * 8;           // global row (q then k)
    bool is_q = row0 < M_Q;
    const float* src = is_q ? q : k;
    const float* pos = is_q ? q_pos : k_pos;
    float* dst       = is_q ? g_QG : g_KG;
    int r0 = is_q ? row0 : row0 - M_Q;

    float* rb = &rowbuf[wid][0];
#pragma unroll
    for (int j = 0; j < 8; j++) {
        const float2* s2 = (const float2*)(src + (size_t)(r0 + j) * CH);
        const float2* p2 = (const float2*)(pos + (size_t)(r0 + j) * CH);
        float2 a = s2[lane], b = p2[lane];
        ((float2*)(rb + j * CH))[lane] = make_float2(a.x + b.x, a.y + b.y);
    }
    __syncwarp();

    unsigned long long accA[8], accB[8];
#pragma unroll
    for (int j = 0; j < 8; j++) { accA[j] = 0ull; accB[j] = 0ull; }
    const float* wr0 = AT + lane * WST;
    const float* wr1 = AT + (lane + 32) * WST;

#pragma unroll
    for (int t4 = 0; t4 < CH; t4 += 4) {
        ulonglong2 wa = *reinterpret_cast<const ulonglong2*>(wr0 + t4);
        ulonglong2 wb = *reinterpret_cast<const ulonglong2*>(wr1 + t4);
#pragma unroll
        for (int j = 0; j < 8; j++) {
            ulonglong2 hp = *reinterpret_cast<const ulonglong2*>(rb + j * CH + t4);
            accA[j] = fma2(hp.x, wa.x, accA[j]);
            accA[j] = fma2(hp.y, wa.y, accA[j]);
            accB[j] = fma2(hp.x, wb.x, accB[j]);
            accB[j] = fma2(hp.y, wb.y, accB[j]);
        }
    }
    float b0 = is_q ? bsh[lane] : 0.f;
    float b1 = is_q ? bsh[lane + 32] : 0.f;
#pragma unroll
    for (int j = 0; j < 8; j++) {
        dst[(size_t)(r0 + j) * CH + lane]      = hsum2(accA[j]) + b0;
        dst[(size_t)(r0 + j) * CH + 32 + lane] = hsum2(accB[j]) + b1;
    }
}

// ---------------------------------------------------------------------------
// Kernel 3: fused attention core. 256 threads, 8 warps, 1 query/warp.
//   smem: Wg2^T, Wv^T (WST-padded), biases, per-warp h[16][64], p[16][64]
//   Attention weights spilled to smem between softmax and Phase C so the
//   p-registers are NOT live across the Phase-C accumulators (reg cap 128
//   => 2 blocks/SM, 16 warps/SM).
// ---------------------------------------------------------------------------
#define ASM_FLOATS (2 * CH * WST + 2 * CH + 8 * KNB * CH + 8 * KNB * CH)
#define ASM_BYTES  (ASM_FLOATS * 4)

__global__ __launch_bounds__(256, 2) void attn_kernel(
    const float* __restrict__ value, const unsigned char* __restrict__ mask,
    const int* __restrict__ knn,
    const float* __restrict__ Wg2, const float* __restrict__ bg2,
    const float* __restrict__ Wv,  const float* __restrict__ bv)
{
    extern __shared__ __align__(16) float sm[];
    float* w2t = sm;                       // [64][WST]
    float* wvt = w2t + CH * WST;
    float* bsh = wvt + CH * WST;           // bg2 | bv
    float* hb  = bsh + 2 * CH;             // 8 warps x [16][64] (h / value rows)
    float* pbb = hb + 8 * KNB * CH;        // 8 warps x [16][64] (attn weights)

    int tid = threadIdx.x, lane = tid & 31, wid = tid >> 5;

    for (int i = tid; i < CH * CH; i += 256) {
        int c = i >> 6, f = i & 63;
        w2t[f * WST + c] = Wg2[i];
        wvt[f * WST + c] = Wv[i];
    }
    if (tid < CH) {
        bsh[tid]      = bg2[tid];
        bsh[CH + tid] = bv[tid];
    }
    __syncthreads();

    int m = blockIdx.x * 8 + wid;
    float* h  = hb  + wid * (KNB * CH);
    float* pb = pbb + wid * (KNB * CH);

    // neighbor ids + mask in lanes 0..15
    int nb = 0, mk = 0;
    int mmode = g_mask_mode;
    if (lane < KNB) {
        size_t ix = (size_t)m * KNB + lane;
        nb = knn[(size_t)M_Q * KNB + ix];           // row 1 of knearest_idx
        if (mmode == 0)      mk = mask[ix] != 0;
        else if (mmode == 1) mk = ((const int*)mask)[ix] != 0;
        else                 mk = ((const float*)mask)[ix] != 0.f;
    }

    float2 qg = ((const float2*)(g_QG + (size_t)m * CH))[lane];

    // ---- Phase A: gather + relu-diff into shared ----
#pragma unroll
    for (int e = 0; e < KNB; e++) {
        int n = __shfl_sync(0xffffffffu, nb, e);
        float2 kg = ((const float2*)(g_KG + (size_t)n * CH))[lane];
        ((float2*)(h + e * CH))[lane] =
            make_float2(fmaxf(qg.x - kg.x, 0.f), fmaxf(qg.y - kg.y, 0.f));
    }
    __syncwarp();

    // ---- Phase B: logits = h @ Wg2 ----
    unsigned long long accA[KNB], accB[KNB];
#pragma unroll
    for (int e = 0; e < KNB; e++) { accA[e] = 0ull; accB[e] = 0ull; }
    {
        const float* r0 = w2t + lane * WST;
        const float* r1 = w2t + (lane + 32) * WST;
#pragma unroll
        for (int c4 = 0; c4 < CH; c4 += 4) {
            ulonglong2 wa = *reinterpret_cast<const ulonglong2*>(r0 + c4);
            ulonglong2 wb = *reinterpret_cast<const ulonglong2*>(r1 + c4);
#pragma unroll
            for (int e = 0; e < KNB; e++) {
                ulonglong2 hp = *reinterpret_cast<const ulonglong2*>(h + e * CH + c4);
                accA[e] = fma2(hp.x, wa.x, accA[e]);
                accA[e] = fma2(hp.y, wa.y, accA[e]);
                accB[e] = fma2(hp.x, wb.x, accB[e]);
                accB[e] = fma2(hp.y, wb.y, accB[e]);
            }
        }
    }

    // ---- mask + per-channel softmax over neighbors; spill weights to smem ----
    {
        float p0[KNB], p1[KNB];
        float b0 = bsh[lane], b1 = bsh[32 + lane];
        float mx0 = -3.4e38f, mx1 = -3.4e38f;
#pragma unroll
        for (int e = 0; e < KNB; e++) {
            int mm = __shfl_sync(0xffffffffu, mk, e);
            float e0 = hsum2(accA[e]) + b0;
            float e1 = hsum2(accB[e]) + b1;
            if (mm) { e0 = -1e12f; e1 = -1e12f; }
            p0[e] = e0; p1[e] = e1;
            mx0 = fmaxf(mx0, e0); mx1 = fmaxf(mx1, e1);
        }
        float s0 = 0.f, s1 = 0.f;
#pragma unroll
        for (int e = 0; e < KNB; e++) {
            p0[e] = __expf(p0[e] - mx0); s0 += p0[e];
            p1[e] = __expf(p1[e] - mx1); s1 += p1[e];
        }
        float inv0 = 1.f / s0, inv1 = 1.f / s1;
#pragma unroll
        for (int e = 0; e < KNB; e++) {
            pb[e * CH + lane]      = p0[e] * inv0;
            pb[e * CH + 32 + lane] = p1[e] * inv1;
        }
    }

    // ---- Phase C: stage value rows, v = value @ Wv, weighted aggregate ----
    __syncwarp();
    {
        const float4* vs4 = (const float4*)(value + (size_t)m * KNB * CH);
        float4* h4 = (float4*)h;
#pragma unroll
        for (int i = 0; i < 8; i++) h4[i * 32 + lane] = vs4[i * 32 + lane];
    }
    __syncwarp();

#pragma unroll
    for (int e = 0; e < KNB; e++) { accA[e] = 0ull; accB[e] = 0ull; }
    {
        const float* r0 = wvt + lane * WST;
        const float* r1 = wvt + (lane + 32) * WST;
#pragma unroll
        for (int c4 = 0; c4 < CH; c4 += 4) {
            ulonglong2 wa = *reinterpret_cast<const ulonglong2*>(r0 + c4);
            ulonglong2 wb = *reinterpret_cast<const ulonglong2*>(r1 + c4);
#pragma unroll
            for (int e = 0; e < KNB; e++) {
                ulonglong2 hp = *reinterpret_cast<const ulonglong2*>(h + e * CH + c4);
                accA[e] = fma2(hp.x, wa.x, accA[e]);
                accA[e] = fma2(hp.y, wa.y, accA[e]);
                accB[e] = fma2(hp.x, wb.x, accB[e]);
                accB[e] = fma2(hp.y, wb.y, accB[e]);
            }
        }
    }
    float bv0 = bsh[CH + lane], bv1 = bsh[CH + 32 + lane];
    float res0 = 0.f, res1 = 0.f;
#pragma unroll
    for (int e = 0; e < KNB; e++) {
        res0 += pb[e * CH + lane]      * (hsum2(accA[e]) + bv0);
        res1 += pb[e * CH + 32 + lane] * (hsum2(accB[e]) + bv1);
    }
    g_RES[(size_t)m * CH + lane]      = res0;
    g_RES[(size_t)m * CH + 32 + lane] = res1;
}

// ---------------------------------------------------------------------------
// Kernel 4: out = g_RES @ Wt + bt
// ---------------------------------------------------------------------------
__global__ __launch_bounds__(256) void outproj_kernel(
    const float* __restrict__ Wt, const float* __restrict__ bt,
    float* __restrict__ out)
{
    __shared__ __align__(16) float WT[CH * WST];
    __shared__ __align__(16) float rowbuf[8][8 * CH];
    __shared__ float bsh[CH];

    int tid = threadIdx.x, lane = tid & 31, wid = tid >> 5;

    for (int i = tid; i < CH * CH; i += 256) {
        int t = i >> 6, c = i & 63;
        WT[c * WST + t] = Wt[i];
    }
    if (tid < CH) bsh[tid] = bt[tid];
    __syncthreads();

    int r0 = blockIdx.x * 64 + wid * 8;
    float* rb = &rowbuf[wid][0];
#pragma unroll
    for (int j = 0; j < 8; j++) {
        ((float2*)(rb + j * CH))[lane] =
            ((const float2*)(g_RES + (size_t)(r0 + j) * CH))[lane];
    }
    __syncwarp();

    unsigned long long accA[8], accB[8];
#pragma unroll
    for (int j = 0; j < 8; j++) { accA[j] = 0ull; accB[j] = 0ull; }
    const float* wr0 = WT + lane * WST;
    const float* wr1 = WT + (lane + 32) * WST;

#pragma unroll
    for (int t4 = 0; t4 < CH; t4 += 4) {
        ulonglong2 wa = *reinterpret_cast<const ulonglong2*>(wr0 + t4);
        ulonglong2 wb = *reinterpret_cast<const ulonglong2*>(wr1 + t4);
#pragma unroll
        for (int j = 0; j < 8; j++) {
            ulonglong2 hp = *reinterpret_cast<const ulonglong2*>(rb + j * CH + t4);
            accA[j] = fma2(hp.x, wa.x, accA[j]);
            accA[j] = fma2(hp.y, wa.y, accA[j]);
            accB[j] = fma2(hp.x, wb.x, accB[j]);
            accB[j] = fma2(hp.y, wb.y, accB[j]);
        }
    }
#pragma unroll
    for (int j = 0; j < 8; j++) {
        out[(size_t)(r0 + j) * CH + lane]      = hsum2(accA[j]) + bsh[lane];
        out[(size_t)(r0 + j) * CH + 32 + lane] = hsum2(accB[j]) + bsh[lane + 32];
    }
}

// ---------------------------------------------------------------------------
// kernel_launch
// Inputs: 0 q, 1 k, 2 value, 3 q_pos, 4 k_pos, 5 mask(bool), 6 knn(i32),
//  7 k_num, 8 Wqk, 9 bqk, 10 Wv, 11 bv, 12 Wg1, 13 bg1, 14 Wg2, 15 bg2,
//  16 Wt, 17 bt.   Output: [M, C] f32.
// ---------------------------------------------------------------------------
extern "C" void kernel_launch(void* const* d_in, const int* in_sizes, int n_in,
                              void* d_out, int out_size)
{
    const float* q      = (const float*)d_in[0];
    const float* k      = (const float*)d_in[1];
    const float* value  = (const float*)d_in[2];
    const float* q_pos  = (const float*)d_in[3];
    const float* k_pos  = (const float*)d_in[4];
    const unsigned char* mask = (const unsigned char*)d_in[5];
    const int*   knn    = (const int*)d_in[6];
    const float* Wqk    = (const float*)d_in[8];
    const float* Wv     = (const float*)d_in[10];
    const float* bv     = (const float*)d_in[11];
    const float* Wg1    = (const float*)d_in[12];
    const float* bg1    = (const float*)d_in[13];
    const float* Wg2    = (const float*)d_in[14];
    const float* bg2    = (const float*)d_in[15];
    const float* Wt     = (const float*)d_in[16];
    const float* bt     = (const float*)d_in[17];
    float* out = (float*)d_out;

    cudaFuncSetAttribute(attn_kernel,
                         cudaFuncAttributeMaxDynamicSharedMemorySize, ASM_BYTES);

    detect_mask_kernel<<<1, 1024>>>(mask);
    compute_A_kernel<<<8, 512>>>(Wqk, Wg1);
    project_kernel<<<(M_Q + N_K) / 64, 256>>>(q, q_pos, k, k_pos, bg1);
    attn_kernel<<<M_Q / 8, 256, ASM_BYTES>>>(value, mask, knn,
                                             Wg2, bg2, Wv, bv);
    outproj_kernel<<<M_Q / 64, 256>>>(Wt, bt, out);
}

// round 7
// speedup vs baseline: 1.7457x; 1.2962x over previous
#include <cuda_runtime.h>
#include <cuda_bf16.h>
#include <cstdint>

// Problem constants
#define M_Q 65536
#define N_K 65536
#define KNB 16
#define CH  64
#define WST 68   // padded row stride for fma2 weight tiles

// ---------------------------------------------------------------------------
// Device-global scratch
// ---------------------------------------------------------------------------
__device__ float g_A  [CH * CH];        // A = Wqk @ Wg1
__device__ float g_QG [M_Q * CH];       // (q+q_pos)@A + bg1
__device__ float g_KG [N_K * CH];       // (k+k_pos)@A
__device__ float g_RES[M_Q * CH];       // pre-output aggregate
__device__ int   g_mask_mode;           // 0 = uint8, 1 = int32, 2 = float32
// Precomputed B fragments for mma.sync: [nb(8)][gemm(2)][lane(32)][16 words]
//   word w: split = w>>3 (0 hi, 1 lo), kb = (w>>1)&3, r = w&1
__device__ unsigned int g_BF[8 * 2 * 32 * 16];

#define SWZ128(x) ((x) ^ (((x) >> 3) & 0x70))

// ---------------------------------------------------------------------------
// fp32x2 helpers (projection kernels)
// ---------------------------------------------------------------------------
__device__ __forceinline__ unsigned long long fma2(unsigned long long a,
                                                   unsigned long long b,
                                                   unsigned long long c) {
    unsigned long long d;
    asm("fma.rn.f32x2 %0, %1, %2, %3;" : "=l"(d) : "l"(a), "l"(b), "l"(c));
    return d;
}
__device__ __forceinline__ float hsum2(unsigned long long v) {
    float lo, hi;
    asm("mov.b64 {%0, %1}, %2;" : "=f"(lo), "=f"(hi) : "l"(v));
    return lo + hi;
}

// ---------------------------------------------------------------------------
// bf16 split helpers
// ---------------------------------------------------------------------------
__device__ __forceinline__ unsigned int pack_hi(float x0, float x1,
                                                float& r0, float& r1) {
    __nv_bfloat16 b0 = __float2bfloat16(x0), b1 = __float2bfloat16(x1);
    r0 = x0 - __bfloat162float(b0);
    r1 = x1 - __bfloat162float(b1);
    return ((unsigned int)__bfloat16_as_ushort(b1) << 16) |
           (unsigned int)__bfloat16_as_ushort(b0);
}
__device__ __forceinline__ unsigned int pack_lo(float r0, float r1) {
    return ((unsigned int)__bfloat16_as_ushort(__float2bfloat16(r1)) << 16) |
           (unsigned int)__bfloat16_as_ushort(__float2bfloat16(r0));
}

// ---------------------------------------------------------------------------
// mma.sync / ldmatrix wrappers (arch-neutral, sm_80+)
// ---------------------------------------------------------------------------
__device__ __forceinline__ uint32_t smem_u32(const void* p) {
    uint32_t a;
    asm("{ .reg .u64 t; cvta.to.shared.u64 t, %1; cvt.u32.u64 %0, t; }"
        : "=r"(a) : "l"(p));
    return a;
}
__device__ __forceinline__ void ldsm_x4(uint32_t& a0, uint32_t& a1,
                                        uint32_t& a2, uint32_t& a3, uint32_t addr) {
    asm volatile("ldmatrix.sync.aligned.m8n8.x4.shared.b16 {%0,%1,%2,%3}, [%4];"
                 : "=r"(a0), "=r"(a1), "=r"(a2), "=r"(a3) : "r"(addr));
}
__device__ __forceinline__ void mma16816(float& c0, float& c1, float& c2, float& c3,
                                         uint32_t a0, uint32_t a1, uint32_t a2,
                                         uint32_t a3, uint32_t b0, uint32_t b1) {
    asm volatile(
        "mma.sync.aligned.m16n8k16.row.col.f32.bf16.bf16.f32 "
        "{%0,%1,%2,%3}, {%4,%5,%6,%7}, {%8,%9}, {%0,%1,%2,%3};"
        : "+f"(c0), "+f"(c1), "+f"(c2), "+f"(c3)
        : "r"(a0), "r"(a1), "r"(a2), "r"(a3), "r"(b0), "r"(b1));
}

// ---------------------------------------------------------------------------
// Kernel 0: detect mask dtype
// ---------------------------------------------------------------------------
__global__ void detect_mask_kernel(const unsigned char* __restrict__ mask) {
    __shared__ int sA, sB;
    int tid = threadIdx.x;
    if (tid == 0) { sA = 0; sB = 0; }
    __syncthreads();
    const uint4* p = (const uint4*)mask;
    int nvec = (M_Q * KNB) / 16;
    int fA = 0, fB = 0;
    for (int i = tid; i < nvec; i += blockDim.x) {
        uint4 v = p[i];
        unsigned w[4] = {v.x, v.y, v.z, v.w};
#pragma unroll
        for (int j = 0; j < 4; j++) {
            if ((w[j] >> 24) == 0x3fu) fA = 1;
            if (w[j] & 0x00ffff00u)    fB = 1;
            if ((w[j] >> 24) && ((w[j] >> 24) != 0x3fu)) fB = 1;
        }
    }
    if (fA) atomicOr(&sA, 1);
    if (fB) atomicOr(&sB, 1);
    __syncthreads();
    if (tid == 0) g_mask_mode = sA ? 2 : (sB ? 0 : 1);
}

// ---------------------------------------------------------------------------
// Kernel 1: A = Wqk @ Wg1
// ---------------------------------------------------------------------------
__global__ void compute_A_kernel(const float* __restrict__ Wqk,
                                 const float* __restrict__ Wg1) {
    int t = blockIdx.x * blockDim.x + threadIdx.x;
    int r = t >> 6, c = t & 63;
    float s = 0.f;
#pragma unroll
    for (int u = 0; u < CH; u++) s += Wqk[r * CH + u] * Wg1[u * CH + c];
    g_A[t] = s;
}

// ---------------------------------------------------------------------------
// Kernel 1b: precompute B fragments (hi/lo bf16 split) for Wg2 and Wv.
// Fragment element (k, n): b-regs for mma.m16n8k16 row.col:
//   r=0: halves (k = kb*16+2t, n = nb*8+g), (k+1, n)
//   r=1: halves (k = kb*16+2t+8, n), (k+1, n)       [t = lane&3, g = lane>>2]
// ---------------------------------------------------------------------------
__global__ void prep_bfrag_kernel(const float* __restrict__ Wg2,
                                  const float* __restrict__ Wv) {
    int idx = blockIdx.x * 256 + threadIdx.x;       // 0..8191
    int nb   = idx >> 10;
    int rem  = idx & 1023;
    int gm   = rem >> 9;
    int rem2 = rem & 511;
    int lane = rem2 >> 4;
    int w    = rem2 & 15;
    int split = w >> 3, kb = (w >> 1) & 3, r = w & 1;
    int t = lane & 3, gg = lane >> 2;
    int k0 = kb * 16 + 2 * t + (r ? 8 : 0);
    int n  = nb * 8 + gg;
    const float* W = gm ? Wv : Wg2;
    float w0 = W[k0 * CH + n];
    float w1 = W[(k0 + 1) * CH + n];
    unsigned int word;
    if (split == 0) { float r0, r1; word = pack_hi(w0, w1, r0, r1); }
    else {
        __nv_bfloat16 b0 = __float2bfloat16(w0), b1 = __float2bfloat16(w1);
        word = pack_lo(w0 - __bfloat162float(b0), w1 - __bfloat162float(b1));
    }
    g_BF[idx] = word;
}

// ---------------------------------------------------------------------------
// Kernel 2: merged projection (fma2 path, unchanged)
// ---------------------------------------------------------------------------
__global__ __launch_bounds__(256) void project_kernel(
    const float* __restrict__ q, const float* __restrict__ q_pos,
    const float* __restrict__ k, const float* __restrict__ k_pos,
    const float* __restrict__ bg1)
{
    __shared__ __align__(16) float AT[CH * WST];
    __shared__ __align__(16) float rowbuf[8][8 * CH];
    __shared__ float bsh[CH];

    int tid = threadIdx.x, lane = tid & 31, wid = tid >> 5;

    for (int i = tid; i < CH * CH; i += 256) {
        int t = i >> 6, c = i & 63;
        AT[c * WST + t] = g_A[i];
    }
    if (tid < CH) bsh[tid] = bg1[tid];
    __syncthreads();

    int row0 = blockIdx.x * 64 + wid * 8;
    bool is_q = row0 < M_Q;
    const float* src = is_q ? q : k;
    const float* pos = is_q ? q_pos : k_pos;
    float* dst       = is_q ? g_QG : g_KG;
    int r0 = is_q ? row0 : row0 - M_Q;

    float* rb = &rowbuf[wid][0];
#pragma unroll
    for (int j = 0; j < 8; j++) {
        const float2* s2 = (const float2*)(src + (size_t)(r0 + j) * CH);
        const float2* p2 = (const float2*)(pos + (size_t)(r0 + j) * CH);
        float2 a = s2[lane], b = p2[lane];
        ((float2*)(rb + j * CH))[lane] = make_float2(a.x + b.x, a.y + b.y);
    }
    __syncwarp();

    unsigned long long accA[8], accB[8];
#pragma unroll
    for (int j = 0; j < 8; j++) { accA[j] = 0ull; accB[j] = 0ull; }
    const float* wr0 = AT + lane * WST;
    const float* wr1 = AT + (lane + 32) * WST;

#pragma unroll
    for (int t4 = 0; t4 < CH; t4 += 4) {
        ulonglong2 wa = *reinterpret_cast<const ulonglong2*>(wr0 + t4);
        ulonglong2 wb = *reinterpret_cast<const ulonglong2*>(wr1 + t4);
#pragma unroll
        for (int j = 0; j < 8; j++) {
            ulonglong2 hp = *reinterpret_cast<const ulonglong2*>(rb + j * CH + t4);
            accA[j] = fma2(hp.x, wa.x, accA[j]);
            accA[j] = fma2(hp.y, wa.y, accA[j]);
            accB[j] = fma2(hp.x, wb.x, accB[j]);
            accB[j] = fma2(hp.y, wb.y, accB[j]);
        }
    }
    float b0 = is_q ? bsh[lane] : 0.f;
    float b1 = is_q ? bsh[lane + 32] : 0.f;
#pragma unroll
    for (int j = 0; j < 8; j++) {
        dst[(size_t)(r0 + j) * CH + lane]      = hsum2(accA[j]) + b0;
        dst[(size_t)(r0 + j) * CH + 32 + lane] = hsum2(accB[j]) + b1;
    }
}

// ---------------------------------------------------------------------------
// Kernel 3: HMMA attention. 1 CTA = 8 queries = 128 MMA rows, 8 warps.
//   Warp w owns n-cols [8w, 8w+8) of both GEMMs (B frags in registers).
//   GEMM1: logits = h @ Wg2 (bf16 3-term split); GEMM2: vproj = value @ Wv,
//   fused with per-channel softmax epilogue (bg2 cancels; bv added after).
// ---------------------------------------------------------------------------
__global__ __launch_bounds__(256, 2) void attn_mma_kernel(
    const float* __restrict__ value, const unsigned char* __restrict__ mask,
    const int* __restrict__ knn, const float* __restrict__ bv)
{
    __shared__ __align__(1024) char smbuf[33280];
    char* t_hi = smbuf;                 // 16 KB: A tile hi
    char* t_lo = smbuf + 16384;         // 16 KB: A tile lo
    int*  smask = (int*)(smbuf + 32768);

    int tid = threadIdx.x, lane = tid & 31, wid = tid >> 5;
    int m0 = blockIdx.x * 8;
    int t = lane & 3, gg = lane >> 2;

    uint32_t sb_hi = smem_u32(t_hi);
    uint32_t sb_lo = smem_u32(t_lo);

    // ---- mask preload (dtype-agnostic) ----
    if (tid < 128) {
        int qloc = tid >> 4, e = tid & 15;
        size_t ix = (size_t)(m0 + qloc) * KNB + e;
        int mmode = g_mask_mode, mk;
        if (mmode == 0)      mk = mask[ix] != 0;
        else if (mmode == 1) mk = ((const int*)mask)[ix] != 0;
        else                 mk = ((const float*)mask)[ix] != 0.f;
        smask[tid] = mk;
    }

    // ---- build h tiles: warp w = query w ----
    int mq = m0 + wid;
    int nb = 0;
    if (lane < KNB) nb = knn[(size_t)M_Q * KNB + (size_t)mq * KNB + lane];
    float2 qg = ((const float2*)(g_QG + (size_t)mq * CH))[lane];

#pragma unroll
    for (int e = 0; e < KNB; e++) {
        int n = __shfl_sync(0xffffffffu, nb, e);
        float2 kg = ((const float2*)(g_KG + (size_t)n * CH))[lane];
        float x0 = fmaxf(qg.x - kg.x, 0.f), x1 = fmaxf(qg.y - kg.y, 0.f);
        unsigned off = SWZ128((unsigned)((wid * KNB + e) * 128 + lane * 4));
        float r0, r1;
        unsigned hiw = pack_hi(x0, x1, r0, r1);
        *(unsigned*)(t_hi + off) = hiw;
        *(unsigned*)(t_lo + off) = pack_lo(r0, r1);
    }
    __syncthreads();

    // ---- B fragments for GEMM1 (Wg2) ----
    uint32_t bh[8], bl[8];
    {
        const uint4* bp = (const uint4*)g_BF + (wid * 256 + 0 * 128 + lane * 4);
        uint4 q0 = bp[0], q1 = bp[1], q2 = bp[2], q3 = bp[3];
        bh[0]=q0.x; bh[1]=q0.y; bh[2]=q0.z; bh[3]=q0.w;
        bh[4]=q1.x; bh[5]=q1.y; bh[6]=q1.z; bh[7]=q1.w;
        bl[0]=q2.x; bl[1]=q2.y; bl[2]=q2.z; bl[3]=q2.w;
        bl[4]=q3.x; bl[5]=q3.y; bl[6]=q3.z; bl[7]=q3.w;
    }

    // ldmatrix address base: lane -> (row within 16, k-half)
    unsigned lmrow = (unsigned)(lane & 15);
    unsigned lmcol = (unsigned)((lane >> 4) & 1) * 16;

    // ---- GEMM1: D1 = h @ Wg2 ----
    float D1[32];
#pragma unroll
    for (int b = 0; b < 8; b++) {
        float c0 = 0.f, c1 = 0.f, c2 = 0.f, c3 = 0.f;
        unsigned rowoff = (unsigned)(b * 16 + lmrow) * 128 + lmcol;
#pragma unroll
        for (int kb = 0; kb < 4; kb++) {
            unsigned off = SWZ128(rowoff + kb * 32);
            uint32_t a0, a1, a2, a3, l0, l1, l2, l3;
            ldsm_x4(a0, a1, a2, a3, sb_hi + off);
            ldsm_x4(l0, l1, l2, l3, sb_lo + off);
            mma16816(c0, c1, c2, c3, a0, a1, a2, a3, bh[kb*2], bh[kb*2+1]);
            mma16816(c0, c1, c2, c3, a0, a1, a2, a3, bl[kb*2], bl[kb*2+1]);
            mma16816(c0, c1, c2, c3, l0, l1, l2, l3, bh[kb*2], bh[kb*2+1]);
        }
        D1[b*4+0] = c0; D1[b*4+1] = c1; D1[b*4+2] = c2; D1[b*4+3] = c3;
    }
    __syncthreads();

    // ---- rebuild tiles with value rows ----
#pragma unroll
    for (int e = 0; e < KNB; e++) {
        float2 v2 = ((const float2*)(value + ((size_t)mq * KNB + e) * CH))[lane];
        unsigned off = SWZ128((unsigned)((wid * KNB + e) * 128 + lane * 4));
        float r0, r1;
        unsigned hiw = pack_hi(v2.x, v2.y, r0, r1);
        *(unsigned*)(t_hi + off) = hiw;
        *(unsigned*)(t_lo + off) = pack_lo(r0, r1);
    }
    __syncthreads();

    // ---- B fragments for GEMM2 (Wv) ----
    {
        const uint4* bp = (const uint4*)g_BF + (wid * 256 + 1 * 128 + lane * 4);
        uint4 q0 = bp[0], q1 = bp[1], q2 = bp[2], q3 = bp[3];
        bh[0]=q0.x; bh[1]=q0.y; bh[2]=q0.z; bh[3]=q0.w;
        bh[4]=q1.x; bh[5]=q1.y; bh[6]=q1.z; bh[7]=q1.w;
        bl[0]=q2.x; bl[1]=q2.y; bl[2]=q2.z; bl[3]=q2.w;
        bl[4]=q3.x; bl[5]=q3.y; bl[6]=q3.z; bl[7]=q3.w;
    }

    float2 bvv = *(const float2*)(bv + wid * 8 + 2 * t);

    // ---- GEMM2 + fused softmax epilogue per m-block ----
#pragma unroll
    for (int b = 0; b < 8; b++) {
        float c0 = 0.f, c1 = 0.f, c2 = 0.f, c3 = 0.f;
        unsigned rowoff = (unsigned)(b * 16 + lmrow) * 128 + lmcol;
#pragma unroll
        for (int kb = 0; kb < 4; kb++) {
            unsigned off = SWZ128(rowoff + kb * 32);
            uint32_t a0, a1, a2, a3, l0, l1, l2, l3;
            ldsm_x4(a0, a1, a2, a3, sb_hi + off);
            ldsm_x4(l0, l1, l2, l3, sb_lo + off);
            mma16816(c0, c1, c2, c3, a0, a1, a2, a3, bh[kb*2], bh[kb*2+1]);
            mma16816(c0, c1, c2, c3, a0, a1, a2, a3, bl[kb*2], bl[kb*2+1]);
            mma16816(c0, c1, c2, c3, l0, l1, l2, l3, bh[kb*2], bh[kb*2+1]);
        }
        // epilogue: fragment (rows g, g+8; cols 2t, 2t+1) of query m0+b
        int mka = smask[b * 16 + gg];
        int mkb = smask[b * 16 + gg + 8];
        float e0 = mka ? -1e12f : D1[b*4+0];
        float e1 = mka ? -1e12f : D1[b*4+1];
        float e2 = mkb ? -1e12f : D1[b*4+2];
        float e3 = mkb ? -1e12f : D1[b*4+3];

        float mx0 = fmaxf(e0, e2), mx1 = fmaxf(e1, e3);
#pragma unroll
        for (int s = 4; s < 32; s <<= 1) {
            mx0 = fmaxf(mx0, __shfl_xor_sync(0xffffffffu, mx0, s));
            mx1 = fmaxf(mx1, __shfl_xor_sync(0xffffffffu, mx1, s));
        }
        float p0 = __expf(e0 - mx0), p2 = __expf(e2 - mx0);
        float p1 = __expf(e1 - mx1), p3 = __expf(e3 - mx1);
        float s0 = p0 + p2, s1 = p1 + p3;
        float w0 = p0 * c0 + p2 * c2;
        float w1 = p1 * c1 + p3 * c3;
#pragma unroll
        for (int s = 4; s < 32; s <<= 1) {
            s0 += __shfl_xor_sync(0xffffffffu, s0, s);
            s1 += __shfl_xor_sync(0xffffffffu, s1, s);
            w0 += __shfl_xor_sync(0xffffffffu, w0, s);
            w1 += __shfl_xor_sync(0xffffffffu, w1, s);
        }
        if (lane < 4) {
            float2 o = make_float2(w0 / s0 + bvv.x, w1 / s1 + bvv.y);
            *(float2*)(g_RES + (size_t)(m0 + b) * CH + wid * 8 + 2 * t) = o;
        }
    }
}

// ---------------------------------------------------------------------------
// Kernel 4: out = g_RES @ Wt + bt  (unchanged)
// ---------------------------------------------------------------------------
__global__ __launch_bounds__(256) void outproj_kernel(
    const float* __restrict__ Wt, const float* __restrict__ bt,
    float* __restrict__ out)
{
    __shared__ __align__(16) float WT[CH * WST];
    __shared__ __align__(16) float rowbuf[8][8 * CH];
    __shared__ float bsh[CH];

    int tid = threadIdx.x, lane = tid & 31, wid = tid >> 5;

    for (int i = tid; i < CH * CH; i += 256) {
        int t = i >> 6, c = i & 63;
        WT[c * WST + t] = Wt[i];
    }
    if (tid < CH) bsh[tid] = bt[tid];
    __syncthreads();

    int r0 = blockIdx.x * 64 + wid * 8;
    float* rb = &rowbuf[wid][0];
#pragma unroll
    for (int j = 0; j < 8; j++) {
        ((float2*)(rb + j * CH))[lane] =
            ((const float2*)(g_RES + (size_t)(r0 + j) * CH))[lane];
    }
    __syncwarp();

    unsigned long long accA[8], accB[8];
#pragma unroll
    for (int j = 0; j < 8; j++) { accA[j] = 0ull; accB[j] = 0ull; }
    const float* wr0 = WT + lane * WST;
    const float* wr1 = WT + (lane + 32) * WST;

#pragma unroll
    for (int t4 = 0; t4 < CH; t4 += 4) {
        ulonglong2 wa = *reinterpret_cast<const ulonglong2*>(wr0 + t4);
        ulonglong2 wb = *reinterpret_cast<const ulonglong2*>(wr1 + t4);
#pragma unroll
        for (int j = 0; j < 8; j++) {
            ulonglong2 hp = *reinterpret_cast<const ulonglong2*>(rb + j * CH + t4);
            accA[j] = fma2(hp.x, wa.x, accA[j]);
            accA[j] = fma2(hp.y, wa.y, accA[j]);
            accB[j] = fma2(hp.x, wb.x, accB[j]);
            accB[j] = fma2(hp.y, wb.y, accB[j]);
        }
    }
#pragma unroll
    for (int j = 0; j < 8; j++) {
        out[(size_t)(r0 + j) * CH + lane]      = hsum2(accA[j]) + bsh[lane];
        out[(size_t)(r0 + j) * CH + 32 + lane] = hsum2(accB[j]) + bsh[lane + 32];
    }
}

// ---------------------------------------------------------------------------
// kernel_launch
// ---------------------------------------------------------------------------
extern "C" void kernel_launch(void* const* d_in, const int* in_sizes, int n_in,
                              void* d_out, int out_size)
{
    const float* q      = (const float*)d_in[0];
    const float* k      = (const float*)d_in[1];
    const float* value  = (const float*)d_in[2];
    const float* q_pos  = (const float*)d_in[3];
    const float* k_pos  = (const float*)d_in[4];
    const unsigned char* mask = (const unsigned char*)d_in[5];
    const int*   knn    = (const int*)d_in[6];
    const float* Wqk    = (const float*)d_in[8];
    const float* Wv     = (const float*)d_in[10];
    const float* bv     = (const float*)d_in[11];
    const float* Wg1    = (const float*)d_in[12];
    const float* bg1    = (const float*)d_in[13];
    const float* Wg2    = (const float*)d_in[14];
    const float* Wt     = (const float*)d_in[16];
    const float* bt     = (const float*)d_in[17];
    float* out = (float*)d_out;

    detect_mask_kernel<<<1, 1024>>>(mask);
    compute_A_kernel<<<8, 512>>>(Wqk, Wg1);
    prep_bfrag_kernel<<<32, 256>>>(Wg2, Wv);
    project_kernel<<<(M_Q + N_K) / 64, 256>>>(q, q_pos, k, k_pos, bg1);
    attn_mma_kernel<<<M_Q / 8, 256>>>(value, mask, knn, bv);
    outproj_kernel<<<M_Q / 64, 256>>>(Wt, bt, out);
}